// round 14
// baseline (speedup 1.0000x reference)
#include <cuda_runtime.h>
#include <cuda_bf16.h>
#include <mma.h>
#include <cstdint>

using namespace nvcuda;

#define T_   4
#define B_   32
#define C_   384
#define N_   256
#define H_   8
#define D_   48
#define TB_  (T_ * B_)
#define TBH_ (TB_ * H_)
#define BCN_ (B_ * C_ * N_)      // 3,145,728
#define TOT_ (T_ * BCN_)         // 12,582,912
#define M3_  (3 * C_)            // 1152

// ---------------- scratch (device globals) ----------------------------------------
__device__ __nv_bfloat16 g_s1[TOT_];           // spikes after lif1   [tb][c][n]
__device__ __nv_bfloat16 g_sq[TOT_];           // q spikes            [tb][c][n]
__device__ __nv_bfloat16 g_sk[TOT_];
__device__ __nv_bfloat16 g_sv[TOT_];
__device__ __nv_bfloat16 g_s2[TOT_];           // attn-lif spikes
__device__ __nv_bfloat16 g_whi[4 * C_ * C_];   // hi bf16 of BN-scaled weights
__device__ __nv_bfloat16 g_wlo[4 * C_ * C_];   // lo residual
__device__ float         g_bns[4 * C_];        // folded BN scale
__device__ float         g_bnb[4 * C_];        // folded BN shift

// ---------------- prep ------------------------------------------------------------
__global__ void bnfold_kernel(const float* qg, const float* qb, const float* qm, const float* qv,
                              const float* kg, const float* kb, const float* km, const float* kv,
                              const float* vg, const float* vb, const float* vm, const float* vv,
                              const float* pg, const float* pb, const float* pm, const float* pv,
                              const float* pbias)
{
    int i = blockIdx.x * 256 + threadIdx.x;
    if (i >= 4 * C_) return;
    int s = i / C_, c = i - s * C_;
    const float *G, *Bt, *M, *V;
    if      (s == 0) { G = qg; Bt = qb; M = qm; V = qv; }
    else if (s == 1) { G = kg; Bt = kb; M = km; V = kv; }
    else if (s == 2) { G = vg; Bt = vb; M = vm; V = vv; }
    else             { G = pg; Bt = pb; M = pm; V = pv; }
    float inv = G[c] / sqrtf(V[c] + 1e-5f);
    float add = Bt[c] - M[c] * inv;
    if (s == 3) add += pbias[c] * inv;
    g_bns[i] = inv;
    g_bnb[i] = add;
}

__global__ void wconv_kernel(const float* __restrict__ w0, const float* __restrict__ w1,
                             const float* __restrict__ w2, const float* __restrict__ w3)
{
    int i = blockIdx.x * 256 + threadIdx.x;
    if (i >= 4 * C_ * C_) return;
    int s = i / (C_ * C_);
    int j = i - s * (C_ * C_);
    int o = j / C_;
    const float* w = (s == 0) ? w0 : (s == 1) ? w1 : (s == 2) ? w2 : w3;
    float val = w[j] * g_bns[s * C_ + o];
    __nv_bfloat16 hi = __float2bfloat16(val);
    g_whi[i] = hi;
    g_wlo[i] = __float2bfloat16(val - __bfloat162float(hi));
}

// ---------------- LIF (input) ------------------------------------------------------
__global__ void lif_kernel(const float* __restrict__ xin, __nv_bfloat16* __restrict__ sout)
{
    int i = blockIdx.x * 256 + threadIdx.x;
    if (i >= BCN_) return;
    float v = 0.f;
#pragma unroll
    for (int t = 0; t < T_; t++) {
        float xv = xin[(size_t)t * BCN_ + i];
        float h = v + (xv - v) * 0.5f;
        bool sp = (h >= 1.0f);
        sout[(size_t)t * BCN_ + i] = __float2bfloat16(sp ? 1.f : 0.f);
        v = sp ? 0.f : h;
    }
}

// ---------------- cp.async helpers ------------------------------------------------
__device__ __forceinline__ void cpa16(void* s, const void* g)
{
    unsigned int sa = (unsigned int)__cvta_generic_to_shared(s);
    asm volatile("cp.async.cg.shared.global [%0], [%1], 16;\n" :: "r"(sa), "l"(g));
}
__device__ __forceinline__ void cpa_commit() { asm volatile("cp.async.commit_group;\n"); }
template <int NN>
__device__ __forceinline__ void cpa_wait() { asm volatile("cp.async.wait_group %0;\n" :: "n"(NN)); }

// ---------------- fused qkv GEMM + BN + LIF (identical to R13) --------------------
#define FBM 64
#define FBN 256
#define FBK 64
#define FLDA 72
#define FLDB 264
#define FLDC 260
#define FNT 6
#define FA_ST (FBM * FLDA)
#define FAST (2 * FA_ST)
#define FBST (FBK * FLDB)
#define FSTG (FAST + FBST)
#define FCS_OFF (FSTG * 2)
#define FBIAS_OFF (3 * FSTG * 2)
#define FONES_OFF (FBIAS_OFF + 2 * 64 * 16 * 2)
#define FSM (FONES_OFF + 16 * 264 * 2)       // 169216 B

__global__ __launch_bounds__(256, 1)
void gemm_lif_kernel(const __nv_bfloat16* __restrict__ Ahi,
                     const __nv_bfloat16* __restrict__ Alo,
                     const __nv_bfloat16* __restrict__ Bmat,
                     __nv_bfloat16* __restrict__ oq,
                     __nv_bfloat16* __restrict__ ok,
                     __nv_bfloat16* __restrict__ ov)
{
    extern __shared__ char smem[];
    __nv_bfloat16* Sg = (__nv_bfloat16*)smem;
    float*         Cs = (float*)(smem + FCS_OFF);
    __nv_bfloat16* Bh = (__nv_bfloat16*)(smem + FBIAS_OFF);
    __nv_bfloat16* Bl = Bh + 64 * 16;
    __nv_bfloat16* On = (__nv_bfloat16*)(smem + FONES_OFF);

    int o0 = blockIdx.x * FBM;
    int b  = blockIdx.z;
    int s  = o0 / C_;
    int oc0 = o0 - s * C_;
    __nv_bfloat16* outp = (s == 0) ? oq : (s == 1) ? ok : ov;

    int tid = threadIdx.x;
    int wid = tid >> 5;
    int wm = wid & 1;
    int wn = wid >> 1;

#pragma unroll
    for (int u = 0; u < 4; u++) {
        int idx = tid + u * 256;
        int r = idx >> 4, c = idx & 15;
        float bv = (c == 0) ? g_bnb[o0 + r] : 0.f;
        __nv_bfloat16 hh = __float2bfloat16(bv);
        Bh[idx] = hh;
        Bl[idx] = __float2bfloat16(bv - __bfloat162float(hh));
    }
    for (int idx = tid; idx < 16 * 264; idx += 256) {
        int r = idx / 264, c = idx - r * 264;
        On[idx] = __float2bfloat16((r == 0 && c < 256) ? 1.f : 0.f);
    }
    __syncthreads();

    float vm[2][4][8];
#pragma unroll
    for (int i = 0; i < 2; i++)
#pragma unroll
        for (int j = 0; j < 4; j++)
#pragma unroll
            for (int e = 0; e < 8; e++) vm[i][j][e] = 0.f;

    auto fill = [&](const __nv_bfloat16* Bp, int kt, int st) {
        __nv_bfloat16* Ah = Sg + st * FSTG;
        __nv_bfloat16* Al = Ah + FA_ST;
        __nv_bfloat16* Bd = Ah + FAST;
        int ka = kt * FBK;
#pragma unroll
        for (int u = 0; u < 2; u++) {
            int idx = tid + u * 256;
            int r = idx >> 3, c8 = (idx & 7) << 3;
            size_t go = (size_t)(o0 + r) * C_ + ka + c8;
            cpa16(Ah + r * FLDA + c8, Ahi + go);
            cpa16(Al + r * FLDA + c8, Alo + go);
        }
#pragma unroll
        for (int u = 0; u < 8; u++) {
            int idx = tid + u * 256;
            int r = idx >> 5, c8 = (idx & 31) << 3;
            cpa16(Bd + r * FLDB + c8, Bp + (size_t)(ka + r) * N_ + c8);
        }
        cpa_commit();
    };

    {
        const __nv_bfloat16* Bp0 = Bmat + (size_t)(0 * B_ + b) * C_ * N_;
        fill(Bp0, 0, 0);
        fill(Bp0, 1, 1);
    }

#pragma unroll 1
    for (int t = 0; t < T_; t++) {
        const __nv_bfloat16* Bp = Bmat + (size_t)(t * B_ + b) * C_ * N_;

        wmma::fragment<wmma::accumulator, 16, 16, 16, float> acc[2][4];
        {
            wmma::fragment<wmma::matrix_b, 16, 16, 16, __nv_bfloat16, wmma::row_major> onef;
            wmma::load_matrix_sync(onef, On, 264);
            wmma::fragment<wmma::matrix_a, 16, 16, 16, __nv_bfloat16, wmma::row_major> bh[2], bl2[2];
#pragma unroll
            for (int i = 0; i < 2; i++) {
                wmma::load_matrix_sync(bh[i],  Bh + (wm * 32 + i * 16) * 16, 16);
                wmma::load_matrix_sync(bl2[i], Bl + (wm * 32 + i * 16) * 16, 16);
            }
#pragma unroll
            for (int i = 0; i < 2; i++)
#pragma unroll
                for (int j = 0; j < 4; j++) {
                    wmma::fill_fragment(acc[i][j], 0.f);
                    wmma::mma_sync(acc[i][j], bh[i],  onef, acc[i][j]);
                    wmma::mma_sync(acc[i][j], bl2[i], onef, acc[i][j]);
                }
        }

        for (int kt = 0; kt < FNT; kt++) {
            if (kt + 1 < FNT) cpa_wait<1>(); else cpa_wait<0>();
            __syncthreads();
            int st = kt % 3;
            const __nv_bfloat16* Ah = Sg + st * FSTG;
            const __nv_bfloat16* Al = Ah + FA_ST;
            const __nv_bfloat16* Bb = Ah + FAST;
#pragma unroll
            for (int ks = 0; ks < 4; ks++) {
                wmma::fragment<wmma::matrix_b, 16, 16, 16, __nv_bfloat16, wmma::row_major> bfr[4];
#pragma unroll
                for (int j = 0; j < 4; j++)
                    wmma::load_matrix_sync(bfr[j], Bb + (ks * 16) * FLDB + wn * 64 + j * 16, FLDB);
                wmma::fragment<wmma::matrix_a, 16, 16, 16, __nv_bfloat16, wmma::row_major> af[2];
#pragma unroll
                for (int i = 0; i < 2; i++)
                    wmma::load_matrix_sync(af[i], Ah + (wm * 32 + i * 16) * FLDA + ks * 16, FLDA);
#pragma unroll
                for (int i = 0; i < 2; i++)
#pragma unroll
                    for (int j = 0; j < 4; j++)
                        wmma::mma_sync(acc[i][j], af[i], bfr[j], acc[i][j]);
#pragma unroll
                for (int i = 0; i < 2; i++)
                    wmma::load_matrix_sync(af[i], Al + (wm * 32 + i * 16) * FLDA + ks * 16, FLDA);
#pragma unroll
                for (int i = 0; i < 2; i++)
#pragma unroll
                    for (int j = 0; j < 4; j++)
                        wmma::mma_sync(acc[i][j], af[i], bfr[j], acc[i][j]);
            }
            if (kt + 2 < FNT) fill(Bp, kt + 2, (kt + 2) % 3);
        }
        __syncthreads();

        if (t + 1 < T_) {
            const __nv_bfloat16* Bp1 = Bmat + (size_t)((t + 1) * B_ + b) * C_ * N_;
            fill(Bp1, 0, 0);
        }

#pragma unroll
        for (int i = 0; i < 2; i++)
#pragma unroll
            for (int j = 0; j < 4; j++)
#pragma unroll
                for (int e = 0; e < 8; e++) {
                    float y = acc[i][j].x[e];
                    float m = vm[i][j][e];
                    float hh = m + (y - m) * 0.5f;
                    bool sp = (hh >= 1.0f);
                    vm[i][j][e] = sp ? 0.f : hh;
                    acc[i][j].x[e] = sp ? 1.f : 0.f;
                }

#pragma unroll
        for (int i = 0; i < 2; i++)
#pragma unroll
            for (int j = 0; j < 4; j++)
                wmma::store_matrix_sync(Cs + (wm * 32 + i * 16) * FLDC + wn * 64 + j * 16,
                                        acc[i][j], FLDC, wmma::mem_row_major);
        __syncthreads();

        {
            size_t obase = (size_t)(t * B_ + b) * C_ * N_;
#pragma unroll
            for (int u = 0; u < 16; u++) {
                int e = tid + u * 256;
                int r = e >> 6;
                int c4 = (e & 63) << 2;
                float4 val = *(float4*)(Cs + r * FLDC + c4);
                __nv_bfloat162 p0 = __floats2bfloat162_rn(val.x, val.y);
                __nv_bfloat162 p1 = __floats2bfloat162_rn(val.z, val.w);
                uint2 w;
                w.x = *(unsigned int*)&p0;
                w.y = *(unsigned int*)&p1;
                *(uint2*)(outp + obase + (size_t)(oc0 + r) * N_ + c4) = w;
            }
        }
        __syncthreads();

        if (t + 1 < T_) {
            const __nv_bfloat16* Bp1 = Bmat + (size_t)((t + 1) * B_ + b) * C_ * N_;
            fill(Bp1, 1, 1);
        }
    }
}

// ---------------- proj GEMM + folded BN (identical to R8) -------------------------
#define GBM 128
#define GBN 256
#define GBK 64
#define LDA 72
#define LDB 264
#define LDC 260
#define NT_ 6
#define A_ST (GBM * LDA)
#define AST (2 * A_ST)
#define BST (GBK * LDB)
#define STG_ (AST + BST)
#define GSM (3 * STG_ * 2)                // 211968 B

__global__ __launch_bounds__(256, 1)
void gemm_bn_kernel(const __nv_bfloat16* __restrict__ Ahi,
                    const __nv_bfloat16* __restrict__ Alo,
                    const __nv_bfloat16* __restrict__ Bmat,
                    int ldo, int bnoff, float* __restrict__ out)
{
    extern __shared__ char smem[];
    __nv_bfloat16* Sg = (__nv_bfloat16*)smem;
    float*         Cs = (float*)smem;

    int o0 = blockIdx.x * GBM;
    int tb = blockIdx.z;
    const __nv_bfloat16* Bp = Bmat + (size_t)tb * C_ * N_;
    int tid = threadIdx.x;
    int wid = tid >> 5;
    int wm = wid & 1;
    int wn = wid >> 1;

    wmma::fragment<wmma::accumulator, 16, 16, 16, float> acc[4][4];
#pragma unroll
    for (int i = 0; i < 4; i++)
#pragma unroll
        for (int j = 0; j < 4; j++) wmma::fill_fragment(acc[i][j], 0.f);

    auto fill = [&](int kt, int st) {
        __nv_bfloat16* Ah = Sg + st * STG_;
        __nv_bfloat16* Al = Ah + A_ST;
        __nv_bfloat16* Bd = Ah + AST;
        int ka = kt * GBK;
#pragma unroll
        for (int u = 0; u < 4; u++) {
            int idx = tid + u * 256;
            int r = idx >> 3, c8 = (idx & 7) << 3;
            size_t go = (size_t)(o0 + r) * C_ + ka + c8;
            cpa16(Ah + r * LDA + c8, Ahi + go);
            cpa16(Al + r * LDA + c8, Alo + go);
        }
#pragma unroll
        for (int u = 0; u < 8; u++) {
            int idx = tid + u * 256;
            int r = idx >> 5, c8 = (idx & 31) << 3;
            cpa16(Bd + r * LDB + c8, Bp + (size_t)(ka + r) * N_ + c8);
        }
        cpa_commit();
    };

    fill(0, 0);
    fill(1, 1);
    for (int kt = 0; kt < NT_; kt++) {
        if (kt + 1 < NT_) cpa_wait<1>(); else cpa_wait<0>();
        __syncthreads();
        int st = kt % 3;
        const __nv_bfloat16* Ah = Sg + st * STG_;
        const __nv_bfloat16* Al = Ah + A_ST;
        const __nv_bfloat16* Bb = Ah + AST;
#pragma unroll
        for (int ks = 0; ks < 4; ks++) {
            wmma::fragment<wmma::matrix_b, 16, 16, 16, __nv_bfloat16, wmma::row_major> bfr[4];
#pragma unroll
            for (int j = 0; j < 4; j++)
                wmma::load_matrix_sync(bfr[j], Bb + (ks * 16) * LDB + wn * 64 + j * 16, LDB);
            wmma::fragment<wmma::matrix_a, 16, 16, 16, __nv_bfloat16, wmma::row_major> af[4];
#pragma unroll
            for (int i = 0; i < 4; i++)
                wmma::load_matrix_sync(af[i], Ah + (wm * 64 + i * 16) * LDA + ks * 16, LDA);
#pragma unroll
            for (int i = 0; i < 4; i++)
#pragma unroll
                for (int j = 0; j < 4; j++)
                    wmma::mma_sync(acc[i][j], af[i], bfr[j], acc[i][j]);
#pragma unroll
            for (int i = 0; i < 4; i++)
                wmma::load_matrix_sync(af[i], Al + (wm * 64 + i * 16) * LDA + ks * 16, LDA);
#pragma unroll
            for (int i = 0; i < 4; i++)
#pragma unroll
                for (int j = 0; j < 4; j++)
                    wmma::mma_sync(acc[i][j], af[i], bfr[j], acc[i][j]);
        }
        if (kt + 2 < NT_) fill(kt + 2, (kt + 2) % 3);
    }
    __syncthreads();

#pragma unroll
    for (int i = 0; i < 4; i++)
#pragma unroll
        for (int j = 0; j < 4; j++)
            wmma::store_matrix_sync(Cs + (wm * 64 + i * 16) * LDC + wn * 64 + j * 16,
                                    acc[i][j], LDC, wmma::mem_row_major);
    __syncthreads();

#pragma unroll
    for (int u = 0; u < 32; u++) {
        int e = tid + u * 256;
        int r = e >> 6;
        int c4 = (e & 63) << 2;
        int o = o0 + r;
        float add = g_bnb[bnoff + o];
        float4 val = *(float4*)(Cs + r * LDC + c4);
        val.x += add; val.y += add; val.z += add; val.w += add;
        *(float4*)(out + ((size_t)tb * ldo + o) * N_ + c4) = val;
    }
}

// ---------------- fused attention + attn-LIF --------------------------------------
// Grid (nt 4, h 8, b 32) = 1024 blocks; t loops inside; membrane 12 regs/thread.
// 0.125 scale folded into the exact S->bf16 conversion. Spikes written to g_s2.
#define LDK 264     // K/V row (256 + 8)
#define LDQ2 72     // Q stripe row (64 + 8)
#define LDSF 68
#define LDS2 72
#define XK_  0                              // Ks [48][264]
#define XV_  (48 * LDK * 2)                 // Vs [64][264] (rows 48..63 zero)
#define XQ_  (XV_ + 64 * LDK * 2)           // Qs [48][72]
#define XSF  (XQ_ + 48 * LDQ2 * 2)          // Sfp [256][68] fp32 (Osm alias)
#define XST  (XSF + 256 * LDSF * 4)         // Stb [256][72] bf16
#define XSM  (XST + 256 * LDS2 * 2)         // 172544 B

__global__ __launch_bounds__(256)
void attn_lif_kernel(const __nv_bfloat16* __restrict__ q, const __nv_bfloat16* __restrict__ k,
                     const __nv_bfloat16* __restrict__ v, __nv_bfloat16* __restrict__ s2out)
{
    extern __shared__ char smraw[];
    __nv_bfloat16* Ks = (__nv_bfloat16*)(smraw + XK_);
    __nv_bfloat16* Vs = (__nv_bfloat16*)(smraw + XV_);
    __nv_bfloat16* Qs = (__nv_bfloat16*)(smraw + XQ_);
    float*         Sfp = (float*)(smraw + XSF);
    float*         Osm = (float*)(smraw + XSF);     // alias
    __nv_bfloat16* Stb = (__nv_bfloat16*)(smraw + XST);

    int blk = blockIdx.x;
    int nt = blk & 3, h = (blk >> 2) & 7, b = blk >> 5;
    int n0 = nt * 64;
    int tid = threadIdx.x;
    int wid = tid >> 5;

    // zero-pad V rows 48..63 once (overwritten? no — rows 48..63 never written by loads)
#pragma unroll
    for (int u = 0; u < 2; u++) {
        int idx = tid + u * 256;
        int r = 48 + (idx >> 5), col = (idx & 31) << 3;
        *(uint4*)(Vs + r * LDK + col) = make_uint4(0, 0, 0, 0);
    }

    float vm[3][4];
#pragma unroll
    for (int u = 0; u < 3; u++)
#pragma unroll
        for (int e = 0; e < 4; e++) vm[u][e] = 0.f;

#pragma unroll 1
    for (int t = 0; t < T_; t++) {
        size_t base = (((size_t)(t * B_ + b)) * C_ + h * D_) * N_;

        // K rows 0..47 full n (1536 uint4)
#pragma unroll
        for (int u = 0; u < 6; u++) {
            int idx = tid + u * 256;
            int r = idx >> 5, col = (idx & 31) << 3;
            *(uint4*)(Ks + r * LDK + col) = *(const uint4*)(k + base + (size_t)r * N_ + col);
        }
        // V rows 0..47 full n
#pragma unroll
        for (int u = 0; u < 6; u++) {
            int idx = tid + u * 256;
            int r = idx >> 5, col = (idx & 31) << 3;
            *(uint4*)(Vs + r * LDK + col) = *(const uint4*)(v + base + (size_t)r * N_ + col);
        }
        // Q stripe rows 0..47 x 64 cols (384 uint4)
#pragma unroll
        for (int u = 0; u < 2; u++) {
            int idx = tid + u * 256;
            if (idx < 384) {
                int r = idx >> 3, c8 = (idx & 7) << 3;
                *(uint4*)(Qs + r * LDQ2 + c8) = *(const uint4*)(q + base + (size_t)r * N_ + n0 + c8);
            }
        }
        __syncthreads();

        // ---- stage 1: St[m 0..255][n' 0..63] = K^T Q ----
        {
            int wm2 = wid & 3;      // m, 64 each
            int wn2 = wid >> 2;     // n', 32 each
            wmma::fragment<wmma::accumulator, 16, 16, 16, float> sacc[4][2];
#pragma unroll
            for (int i = 0; i < 4; i++)
#pragma unroll
                for (int j = 0; j < 2; j++) wmma::fill_fragment(sacc[i][j], 0.f);
#pragma unroll
            for (int dk = 0; dk < 48; dk += 16) {
                wmma::fragment<wmma::matrix_a, 16, 16, 16, __nv_bfloat16, wmma::col_major> ak[4];
                wmma::fragment<wmma::matrix_b, 16, 16, 16, __nv_bfloat16, wmma::row_major> bq[2];
#pragma unroll
                for (int i = 0; i < 4; i++)
                    wmma::load_matrix_sync(ak[i], Ks + dk * LDK + wm2 * 64 + i * 16, LDK);
#pragma unroll
                for (int j = 0; j < 2; j++)
                    wmma::load_matrix_sync(bq[j], Qs + dk * LDQ2 + wn2 * 32 + j * 16, LDQ2);
#pragma unroll
                for (int i = 0; i < 4; i++)
#pragma unroll
                    for (int j = 0; j < 2; j++)
                        wmma::mma_sync(sacc[i][j], ak[i], bq[j], sacc[i][j]);
            }
#pragma unroll
            for (int i = 0; i < 4; i++)
#pragma unroll
                for (int j = 0; j < 2; j++)
                    wmma::store_matrix_sync(Sfp + (wm2 * 64 + i * 16) * LDSF + wn2 * 32 + j * 16,
                                            sacc[i][j], LDSF, wmma::mem_row_major);
        }
        __syncthreads();

        // ---- convert S -> bf16 with exact x0.125 fold ----
#pragma unroll
        for (int u = 0; u < 16; u++) {
            int idx = tid + u * 256;
            int m = idx >> 4, c4 = (idx & 15) << 2;
            float4 val = *(float4*)(Sfp + m * LDSF + c4);
            __nv_bfloat162 p0 = __floats2bfloat162_rn(val.x * 0.125f, val.y * 0.125f);
            __nv_bfloat162 p1 = __floats2bfloat162_rn(val.z * 0.125f, val.w * 0.125f);
            uint2 w;
            w.x = *(unsigned int*)&p0;
            w.y = *(unsigned int*)&p1;
            *(uint2*)(Stb + m * LDS2 + c4) = w;
        }
        __syncthreads();

        // ---- stage 2: O[d 0..63][n' 0..63] = V St ----
        {
            int dr = wid & 1;
            int nc = wid >> 1;
            wmma::fragment<wmma::accumulator, 16, 16, 16, float> oacc[2];
#pragma unroll
            for (int i = 0; i < 2; i++) wmma::fill_fragment(oacc[i], 0.f);
#pragma unroll
            for (int m = 0; m < 256; m += 16) {
                wmma::fragment<wmma::matrix_a, 16, 16, 16, __nv_bfloat16, wmma::row_major> av[2];
                wmma::fragment<wmma::matrix_b, 16, 16, 16, __nv_bfloat16, wmma::row_major> bs;
#pragma unroll
                for (int i = 0; i < 2; i++)
                    wmma::load_matrix_sync(av[i], Vs + (dr * 32 + i * 16) * LDK + m, LDK);
                wmma::load_matrix_sync(bs, Stb + m * LDS2 + nc * 16, LDS2);
#pragma unroll
                for (int i = 0; i < 2; i++)
                    wmma::mma_sync(oacc[i], av[i], bs, oacc[i]);
            }
#pragma unroll
            for (int i = 0; i < 2; i++)
                wmma::store_matrix_sync(Osm + (dr * 32 + i * 16) * LDSF + nc * 16,
                                        oacc[i], LDSF, wmma::mem_row_major);
        }
        __syncthreads();

        // ---- fused LIF epilogue (d < 48), spikes -> s2 ----
        {
#pragma unroll
            for (int u = 0; u < 3; u++) {
                int e = tid + u * 256;        // 768 total = 48 rows x 16 col-groups
                int d = e >> 4, c4 = (e & 15) << 2;
                float4 xv = *(float4*)(Osm + d * LDSF + c4);
                float hh, s0, s1v, s2v, s3v;
                hh = vm[u][0] + (xv.x - vm[u][0]) * 0.5f; s0  = (hh >= 1.f) ? 1.f : 0.f; vm[u][0] = (hh >= 1.f) ? 0.f : hh;
                hh = vm[u][1] + (xv.y - vm[u][1]) * 0.5f; s1v = (hh >= 1.f) ? 1.f : 0.f; vm[u][1] = (hh >= 1.f) ? 0.f : hh;
                hh = vm[u][2] + (xv.z - vm[u][2]) * 0.5f; s2v = (hh >= 1.f) ? 1.f : 0.f; vm[u][2] = (hh >= 1.f) ? 0.f : hh;
                hh = vm[u][3] + (xv.w - vm[u][3]) * 0.5f; s3v = (hh >= 1.f) ? 1.f : 0.f; vm[u][3] = (hh >= 1.f) ? 0.f : hh;
                __nv_bfloat162 p0 = __floats2bfloat162_rn(s0, s1v);
                __nv_bfloat162 p1 = __floats2bfloat162_rn(s2v, s3v);
                uint2 w;
                w.x = *(unsigned int*)&p0;
                w.y = *(unsigned int*)&p1;
                *(uint2*)(s2out + base + (size_t)d * N_ + n0 + c4) = w;
            }
        }
        __syncthreads();
    }
}

// ---------------- launch ----------------------------------------------------------
extern "C" void kernel_launch(void* const* d_in, const int* in_sizes, int n_in,
                              void* d_out, int out_size)
{
    const float* x   = (const float*)d_in[0];
    const float* qw  = (const float*)d_in[2];
    const float* qg  = (const float*)d_in[3];
    const float* qb  = (const float*)d_in[4];
    const float* qm  = (const float*)d_in[5];
    const float* qv  = (const float*)d_in[6];
    const float* kw  = (const float*)d_in[7];
    const float* kg  = (const float*)d_in[8];
    const float* kb  = (const float*)d_in[9];
    const float* km  = (const float*)d_in[10];
    const float* kv  = (const float*)d_in[11];
    const float* vw  = (const float*)d_in[12];
    const float* vg  = (const float*)d_in[13];
    const float* vb  = (const float*)d_in[14];
    const float* vm  = (const float*)d_in[15];
    const float* vv  = (const float*)d_in[16];
    const float* pw  = (const float*)d_in[17];
    const float* pbias = (const float*)d_in[18];
    const float* pg  = (const float*)d_in[19];
    const float* pb  = (const float*)d_in[20];
    const float* pm  = (const float*)d_in[21];
    const float* pv  = (const float*)d_in[22];

    void *ps1, *psq, *psk, *psv, *ps2, *phi, *plo;
    cudaGetSymbolAddress(&ps1, g_s1);
    cudaGetSymbolAddress(&psq, g_sq);
    cudaGetSymbolAddress(&psk, g_sk);
    cudaGetSymbolAddress(&psv, g_sv);
    cudaGetSymbolAddress(&ps2, g_s2);
    cudaGetSymbolAddress(&phi, g_whi);
    cudaGetSymbolAddress(&plo, g_wlo);
    __nv_bfloat16* s1  = (__nv_bfloat16*)ps1;
    __nv_bfloat16* sq  = (__nv_bfloat16*)psq;
    __nv_bfloat16* sk  = (__nv_bfloat16*)psk;
    __nv_bfloat16* sv  = (__nv_bfloat16*)psv;
    __nv_bfloat16* s2  = (__nv_bfloat16*)ps2;
    __nv_bfloat16* whi = (__nv_bfloat16*)phi;
    __nv_bfloat16* wlo = (__nv_bfloat16*)plo;

    cudaFuncSetAttribute(gemm_lif_kernel, cudaFuncAttributeMaxDynamicSharedMemorySize, FSM);
    cudaFuncSetAttribute(gemm_bn_kernel, cudaFuncAttributeMaxDynamicSharedMemorySize, GSM);
    cudaFuncSetAttribute(attn_lif_kernel, cudaFuncAttributeMaxDynamicSharedMemorySize, XSM);

    // prep: BN fold first (wconv consumes g_bns)
    bnfold_kernel<<<6, 256>>>(qg, qb, qm, qv, kg, kb, km, kv,
                              vg, vb, vm, vv, pg, pb, pm, pv, pbias);
    wconv_kernel<<<(4 * C_ * C_ + 255) / 256, 256>>>(qw, kw, vw, pw);
    // proj_lif on input
    lif_kernel<<<BCN_ / 256, 256>>>(x, s1);
    // fused q,k,v GEMM + bias-MMA + LIF
    gemm_lif_kernel<<<dim3(M3_ / FBM, 1, B_), 256, FSM>>>(
        whi, wlo, s1, sq, sk, sv);
    // fused attention + attn-LIF -> bf16 spikes
    attn_lif_kernel<<<B_ * H_ * 4, 256, XSM>>>(sq, sk, sv, s2);
    // proj GEMM + bias + BN -> final output
    gemm_bn_kernel<<<dim3(C_ / GBM, 1, TB_), 256, GSM>>>(
        whi + 3 * C_ * C_, wlo + 3 * C_ * C_, s2, C_, 3 * C_, (float*)d_out);
}

// round 15
// speedup vs baseline: 1.0279x; 1.0279x over previous
#include <cuda_runtime.h>
#include <cuda_bf16.h>
#include <mma.h>
#include <cstdint>

using namespace nvcuda;

#define T_   4
#define B_   32
#define C_   384
#define N_   256
#define H_   8
#define D_   48
#define TB_  (T_ * B_)
#define TBH_ (TB_ * H_)
#define BCN_ (B_ * C_ * N_)      // 3,145,728
#define TOT_ (T_ * BCN_)         // 12,582,912
#define M3_  (3 * C_)            // 1152

// ---------------- scratch (device globals) ----------------------------------------
__device__ __nv_bfloat16 g_s1[TOT_];           // spikes after lif1   [tb][c][n]
__device__ __nv_bfloat16 g_sq[TOT_];           // q spikes            [tb][c][n]
__device__ __nv_bfloat16 g_sk[TOT_];
__device__ __nv_bfloat16 g_sv[TOT_];
__device__ __nv_bfloat16 g_s2[TOT_];           // attn-lif spikes
__device__ float         g_ya[TOT_];           // attention out fp32  [tb][c][n]
__device__ __nv_bfloat16 g_whi[4 * C_ * C_];   // hi bf16 of BN-scaled weights
__device__ __nv_bfloat16 g_wlo[4 * C_ * C_];   // lo residual
__device__ float         g_bns[4 * C_];        // folded BN scale
__device__ float         g_bnb[4 * C_];        // folded BN shift

// ---------------- prep ------------------------------------------------------------
__global__ void bnfold_kernel(const float* qg, const float* qb, const float* qm, const float* qv,
                              const float* kg, const float* kb, const float* km, const float* kv,
                              const float* vg, const float* vb, const float* vm, const float* vv,
                              const float* pg, const float* pb, const float* pm, const float* pv,
                              const float* pbias)
{
    int i = blockIdx.x * 256 + threadIdx.x;
    if (i >= 4 * C_) return;
    int s = i / C_, c = i - s * C_;
    const float *G, *Bt, *M, *V;
    if      (s == 0) { G = qg; Bt = qb; M = qm; V = qv; }
    else if (s == 1) { G = kg; Bt = kb; M = km; V = kv; }
    else if (s == 2) { G = vg; Bt = vb; M = vm; V = vv; }
    else             { G = pg; Bt = pb; M = pm; V = pv; }
    float inv = G[c] / sqrtf(V[c] + 1e-5f);
    float add = Bt[c] - M[c] * inv;
    if (s == 3) add += pbias[c] * inv;
    g_bns[i] = inv;
    g_bnb[i] = add;
}

__global__ void wconv_kernel(const float* __restrict__ w0, const float* __restrict__ w1,
                             const float* __restrict__ w2, const float* __restrict__ w3)
{
    int i = blockIdx.x * 256 + threadIdx.x;
    if (i >= 4 * C_ * C_) return;
    int s = i / (C_ * C_);
    int j = i - s * (C_ * C_);
    int o = j / C_;
    const float* w = (s == 0) ? w0 : (s == 1) ? w1 : (s == 2) ? w2 : w3;
    float val = w[j] * g_bns[s * C_ + o];
    __nv_bfloat16 hi = __float2bfloat16(val);
    g_whi[i] = hi;
    g_wlo[i] = __float2bfloat16(val - __bfloat162float(hi));
}

// ---------------- LIF (streaming) --------------------------------------------------
__global__ void lif_kernel(const float* __restrict__ xin, __nv_bfloat16* __restrict__ sout)
{
    int i = blockIdx.x * 256 + threadIdx.x;
    if (i >= BCN_) return;
    float v = 0.f;
#pragma unroll
    for (int t = 0; t < T_; t++) {
        float xv = xin[(size_t)t * BCN_ + i];
        float h = v + (xv - v) * 0.5f;
        bool sp = (h >= 1.0f);
        sout[(size_t)t * BCN_ + i] = __float2bfloat16(sp ? 1.f : 0.f);
        v = sp ? 0.f : h;
    }
}

// ---------------- cp.async helpers ------------------------------------------------
__device__ __forceinline__ void cpa16(void* s, const void* g)
{
    unsigned int sa = (unsigned int)__cvta_generic_to_shared(s);
    asm volatile("cp.async.cg.shared.global [%0], [%1], 16;\n" :: "r"(sa), "l"(g));
}
__device__ __forceinline__ void cpa_commit() { asm volatile("cp.async.commit_group;\n"); }
template <int NN>
__device__ __forceinline__ void cpa_wait() { asm volatile("cp.async.wait_group %0;\n" :: "n"(NN)); }

// ---------------- fused qkv GEMM + bias-MMA + LIF (A-resident) --------------------
// Tile 64(o) x 256(n). Full A (hi/lo, 64x384) resident in smem, loaded once.
// B: 3-stage cp.async pipeline, 1 sync per k-iter. LIF membrane in registers.
#define FBM 64
#define FBN 256
#define FBK 64
#define FLDA 72
#define FLDB 264
#define FLDC2 132                              // epilogue half staging (fp32)
#define FNT 6
#define FA_KT (FBM * FLDA)                     // 4608 elems per kt tile
#define FA_LOBASE (6 * FA_KT)                  // 27648
#define FB_BASE (2 * FA_LOBASE)                // elems: 55296 (A total)
#define FBST (FBK * FLDB)                      // 16896 elems = 33792 B
#define FCS_B (FB_BASE * 2 + 2 * FBST * 2)     // byte 178176 (aliases B stage 2)
#define FBIAS_B 211968
#define FONES_B 216064
#define FSM 224512

__global__ __launch_bounds__(256, 1)
void gemm_lif_kernel(const __nv_bfloat16* __restrict__ Ahi,
                     const __nv_bfloat16* __restrict__ Alo,
                     const __nv_bfloat16* __restrict__ Bmat,
                     __nv_bfloat16* __restrict__ oq,
                     __nv_bfloat16* __restrict__ ok,
                     __nv_bfloat16* __restrict__ ov)
{
    extern __shared__ char smem[];
    __nv_bfloat16* As = (__nv_bfloat16*)smem;                 // [hi|lo][6][64][72]
    __nv_bfloat16* Bs = As + FB_BASE;                         // 3 x [64][264]
    float*         Cs = (float*)(smem + FCS_B);               // [64][132]
    __nv_bfloat16* Bh = (__nv_bfloat16*)(smem + FBIAS_B);     // bias hi [64][16]
    __nv_bfloat16* Bl = Bh + 64 * 16;
    __nv_bfloat16* On = (__nv_bfloat16*)(smem + FONES_B);     // ones [16][264]

    int o0 = blockIdx.x * FBM;
    int b  = blockIdx.z;
    int s  = o0 / C_;
    int oc0 = o0 - s * C_;
    __nv_bfloat16* outp = (s == 0) ? oq : (s == 1) ? ok : ov;

    int tid = threadIdx.x;
    int wid = tid >> 5;
    int wm = wid & 1;          // 2 warps in M (32 rows each)
    int wn = wid >> 1;         // 4 warps in N (64 cols each)

    // bias + ones tiles
#pragma unroll
    for (int u = 0; u < 4; u++) {
        int idx = tid + u * 256;
        int r = idx >> 4, c = idx & 15;
        float bv = (c == 0) ? g_bnb[o0 + r] : 0.f;
        __nv_bfloat16 hh = __float2bfloat16(bv);
        Bh[idx] = hh;
        Bl[idx] = __float2bfloat16(bv - __bfloat162float(hh));
    }
    for (int idx = tid; idx < 16 * 264; idx += 256) {
        int r = idx / 264, c = idx - r * 264;
        On[idx] = __float2bfloat16((r == 0 && c < 256) ? 1.f : 0.f);
    }

    // load full A (hi + lo) once: 3072 chunks each
#pragma unroll
    for (int u = 0; u < 12; u++) {
        int idx = tid + u * 256;
        int kt = idx >> 9;                     // 512 chunks per kt tile
        int r = (idx >> 3) & 63;
        int c8 = (idx & 7) << 3;
        size_t go = (size_t)(o0 + r) * C_ + kt * FBK + c8;
        cpa16(As + kt * FA_KT + r * FLDA + c8, Ahi + go);
        cpa16(As + FA_LOBASE + kt * FA_KT + r * FLDA + c8, Alo + go);
    }
    cpa_commit();
    __syncthreads();   // bias/ones visible

    float vm[2][4][8];
#pragma unroll
    for (int i = 0; i < 2; i++)
#pragma unroll
        for (int j = 0; j < 4; j++)
#pragma unroll
            for (int e = 0; e < 8; e++) vm[i][j][e] = 0.f;

    auto fillB = [&](const __nv_bfloat16* Bp, int kt, int st) {
        __nv_bfloat16* Bd = Bs + st * FBST;
        int ka = kt * FBK;
#pragma unroll
        for (int u = 0; u < 8; u++) {          // 64x256 = 2048 chunks
            int idx = tid + u * 256;
            int r = idx >> 5, c8 = (idx & 31) << 3;
            cpa16(Bd + r * FLDB + c8, Bp + (size_t)(ka + r) * N_ + c8);
        }
        cpa_commit();
    };

    {
        const __nv_bfloat16* Bp0 = Bmat + (size_t)(0 * B_ + b) * C_ * N_;
        fillB(Bp0, 0, 0);
        fillB(Bp0, 1, 1);
    }

#pragma unroll 1
    for (int t = 0; t < T_; t++) {
        const __nv_bfloat16* Bp = Bmat + (size_t)(t * B_ + b) * C_ * N_;

        // acc init = bias via MMA (hi + lo, exact)
        wmma::fragment<wmma::accumulator, 16, 16, 16, float> acc[2][4];
        {
            wmma::fragment<wmma::matrix_b, 16, 16, 16, __nv_bfloat16, wmma::row_major> onef;
            wmma::load_matrix_sync(onef, On, 264);
            wmma::fragment<wmma::matrix_a, 16, 16, 16, __nv_bfloat16, wmma::row_major> bh[2], bl2[2];
#pragma unroll
            for (int i = 0; i < 2; i++) {
                wmma::load_matrix_sync(bh[i],  Bh + (wm * 32 + i * 16) * 16, 16);
                wmma::load_matrix_sync(bl2[i], Bl + (wm * 32 + i * 16) * 16, 16);
            }
#pragma unroll
            for (int i = 0; i < 2; i++)
#pragma unroll
                for (int j = 0; j < 4; j++) {
                    wmma::fill_fragment(acc[i][j], 0.f);
                    wmma::mma_sync(acc[i][j], bh[i],  onef, acc[i][j]);
                    wmma::mma_sync(acc[i][j], bl2[i], onef, acc[i][j]);
                }
        }

        // mainloop (A resident, B 3-stage)
        for (int kt = 0; kt < FNT; kt++) {
            if (kt + 1 < FNT) cpa_wait<1>(); else cpa_wait<0>();
            __syncthreads();
            const __nv_bfloat16* Ah = As + kt * FA_KT;
            const __nv_bfloat16* Al = As + FA_LOBASE + kt * FA_KT;
            const __nv_bfloat16* Bb = Bs + (kt % 3) * FBST;
#pragma unroll
            for (int ks = 0; ks < 4; ks++) {
                wmma::fragment<wmma::matrix_b, 16, 16, 16, __nv_bfloat16, wmma::row_major> bfr[4];
#pragma unroll
                for (int j = 0; j < 4; j++)
                    wmma::load_matrix_sync(bfr[j], Bb + (ks * 16) * FLDB + wn * 64 + j * 16, FLDB);
                wmma::fragment<wmma::matrix_a, 16, 16, 16, __nv_bfloat16, wmma::row_major> af[2];
#pragma unroll
                for (int i = 0; i < 2; i++)
                    wmma::load_matrix_sync(af[i], Ah + (wm * 32 + i * 16) * FLDA + ks * 16, FLDA);
#pragma unroll
                for (int i = 0; i < 2; i++)
#pragma unroll
                    for (int j = 0; j < 4; j++)
                        wmma::mma_sync(acc[i][j], af[i], bfr[j], acc[i][j]);
#pragma unroll
                for (int i = 0; i < 2; i++)
                    wmma::load_matrix_sync(af[i], Al + (wm * 32 + i * 16) * FLDA + ks * 16, FLDA);
#pragma unroll
                for (int i = 0; i < 2; i++)
#pragma unroll
                    for (int j = 0; j < 4; j++)
                        wmma::mma_sync(acc[i][j], af[i], bfr[j], acc[i][j]);
            }
            if (kt + 2 < FNT) fillB(Bp, kt + 2, (kt + 2) % 3);
        }
        __syncthreads();   // all stage reads done

        // prefetch t+1 B k-tile 0 into stage 0 (not aliased by Cs)
        if (t + 1 < T_) {
            const __nv_bfloat16* Bp1 = Bmat + (size_t)((t + 1) * B_ + b) * C_ * N_;
            fillB(Bp1, 0, 0);
        }

        // LIF in registers; spikes into acc
#pragma unroll
        for (int i = 0; i < 2; i++)
#pragma unroll
            for (int j = 0; j < 4; j++)
#pragma unroll
                for (int e = 0; e < 8; e++) {
                    float y = acc[i][j].x[e];
                    float m = vm[i][j][e];
                    float hh = m + (y - m) * 0.5f;
                    bool sp = (hh >= 1.0f);
                    vm[i][j][e] = sp ? 0.f : hh;
                    acc[i][j].x[e] = sp ? 1.f : 0.f;
                }

        // epilogue in two 128-col halves (Cs aliases B stage 2 only)
        size_t obase = (size_t)(t * B_ + b) * C_ * N_;
#pragma unroll 1
        for (int hhalf = 0; hhalf < 2; hhalf++) {
            if ((wn >> 1) == hhalf) {
                int wnl = wn & 1;
#pragma unroll
                for (int i = 0; i < 2; i++)
#pragma unroll
                    for (int j = 0; j < 4; j++)
                        wmma::store_matrix_sync(Cs + (wm * 32 + i * 16) * FLDC2 + wnl * 64 + j * 16,
                                                acc[i][j], FLDC2, wmma::mem_row_major);
            }
            __syncthreads();
#pragma unroll
            for (int u = 0; u < 8; u++) {        // 64x128 = 2048 float4
                int e = tid + u * 256;
                int r = e >> 5;
                int c4 = (e & 31) << 2;
                int cg = hhalf * 128 + c4;
                float4 val = *(float4*)(Cs + r * FLDC2 + c4);
                __nv_bfloat162 p0 = __floats2bfloat162_rn(val.x, val.y);
                __nv_bfloat162 p1 = __floats2bfloat162_rn(val.z, val.w);
                uint2 w;
                w.x = *(unsigned int*)&p0;
                w.y = *(unsigned int*)&p1;
                *(uint2*)(outp + obase + (size_t)(oc0 + r) * N_ + cg) = w;
            }
            __syncthreads();
        }

        // stage 1 free now; prefetch t+1 B k-tile 1
        if (t + 1 < T_) {
            const __nv_bfloat16* Bp1 = Bmat + (size_t)((t + 1) * B_ + b) * C_ * N_;
            fillB(Bp1, 1, 1);
        }
    }
}

// ---------------- proj GEMM + folded BN (identical to R8) -------------------------
#define GBM 128
#define GBN 256
#define GBK 64
#define LDA 72
#define LDB 264
#define LDC 260
#define NT_ 6
#define A_ST (GBM * LDA)
#define AST (2 * A_ST)
#define BST (GBK * LDB)
#define STG_ (AST + BST)
#define GSM (3 * STG_ * 2)                // 211968 B

__global__ __launch_bounds__(256, 1)
void gemm_bn_kernel(const __nv_bfloat16* __restrict__ Ahi,
                    const __nv_bfloat16* __restrict__ Alo,
                    const __nv_bfloat16* __restrict__ Bmat,
                    int ldo, int bnoff, float* __restrict__ out)
{
    extern __shared__ char smem[];
    __nv_bfloat16* Sg = (__nv_bfloat16*)smem;
    float*         Cs = (float*)smem;

    int o0 = blockIdx.x * GBM;
    int tb = blockIdx.z;
    const __nv_bfloat16* Bp = Bmat + (size_t)tb * C_ * N_;
    int tid = threadIdx.x;
    int wid = tid >> 5;
    int wm = wid & 1;
    int wn = wid >> 1;

    wmma::fragment<wmma::accumulator, 16, 16, 16, float> acc[4][4];
#pragma unroll
    for (int i = 0; i < 4; i++)
#pragma unroll
        for (int j = 0; j < 4; j++) wmma::fill_fragment(acc[i][j], 0.f);

    auto fill = [&](int kt, int st) {
        __nv_bfloat16* Ah = Sg + st * STG_;
        __nv_bfloat16* Al = Ah + A_ST;
        __nv_bfloat16* Bd = Ah + AST;
        int ka = kt * GBK;
#pragma unroll
        for (int u = 0; u < 4; u++) {
            int idx = tid + u * 256;
            int r = idx >> 3, c8 = (idx & 7) << 3;
            size_t go = (size_t)(o0 + r) * C_ + ka + c8;
            cpa16(Ah + r * LDA + c8, Ahi + go);
            cpa16(Al + r * LDA + c8, Alo + go);
        }
#pragma unroll
        for (int u = 0; u < 8; u++) {
            int idx = tid + u * 256;
            int r = idx >> 5, c8 = (idx & 31) << 3;
            cpa16(Bd + r * LDB + c8, Bp + (size_t)(ka + r) * N_ + c8);
        }
        cpa_commit();
    };

    fill(0, 0);
    fill(1, 1);
    for (int kt = 0; kt < NT_; kt++) {
        if (kt + 1 < NT_) cpa_wait<1>(); else cpa_wait<0>();
        __syncthreads();
        int st = kt % 3;
        const __nv_bfloat16* Ah = Sg + st * STG_;
        const __nv_bfloat16* Al = Ah + A_ST;
        const __nv_bfloat16* Bb = Ah + AST;
#pragma unroll
        for (int ks = 0; ks < 4; ks++) {
            wmma::fragment<wmma::matrix_b, 16, 16, 16, __nv_bfloat16, wmma::row_major> bfr[4];
#pragma unroll
            for (int j = 0; j < 4; j++)
                wmma::load_matrix_sync(bfr[j], Bb + (ks * 16) * LDB + wn * 64 + j * 16, LDB);
            wmma::fragment<wmma::matrix_a, 16, 16, 16, __nv_bfloat16, wmma::row_major> af[4];
#pragma unroll
            for (int i = 0; i < 4; i++)
                wmma::load_matrix_sync(af[i], Ah + (wm * 64 + i * 16) * LDA + ks * 16, LDA);
#pragma unroll
            for (int i = 0; i < 4; i++)
#pragma unroll
                for (int j = 0; j < 4; j++)
                    wmma::mma_sync(acc[i][j], af[i], bfr[j], acc[i][j]);
#pragma unroll
            for (int i = 0; i < 4; i++)
                wmma::load_matrix_sync(af[i], Al + (wm * 64 + i * 16) * LDA + ks * 16, LDA);
#pragma unroll
            for (int i = 0; i < 4; i++)
#pragma unroll
                for (int j = 0; j < 4; j++)
                    wmma::mma_sync(acc[i][j], af[i], bfr[j], acc[i][j]);
        }
        if (kt + 2 < NT_) fill(kt + 2, (kt + 2) % 3);
    }
    __syncthreads();

#pragma unroll
    for (int i = 0; i < 4; i++)
#pragma unroll
        for (int j = 0; j < 4; j++)
            wmma::store_matrix_sync(Cs + (wm * 64 + i * 16) * LDC + wn * 64 + j * 16,
                                    acc[i][j], LDC, wmma::mem_row_major);
    __syncthreads();

#pragma unroll
    for (int u = 0; u < 32; u++) {
        int e = tid + u * 256;
        int r = e >> 6;
        int c4 = (e & 63) << 2;
        int o = o0 + r;
        float add = g_bnb[bnoff + o];
        float4 val = *(float4*)(Cs + r * LDC + c4);
        val.x += add; val.y += add; val.z += add; val.w += add;
        *(float4*)(out + ((size_t)tb * ldo + o) * N_ + c4) = val;
    }
}

// ---------------- tensor-core attention (identical to R13) ------------------------
#define LDQ 264
#define LDSF 68
#define LDS2 72
#define LDO 68
#define AQ_  0
#define AK_  (64 * LDQ * 2)
#define AV_  (2 * 64 * LDQ * 2)
#define ASF_ (3 * 64 * LDQ * 2)
#define AST2 (ASF_ + 256 * LDSF * 4)
#define ASM_ (AST2 + 256 * LDS2 * 2)           // 207872 B

__global__ __launch_bounds__(256)
void attn_kernel(const __nv_bfloat16* __restrict__ q, const __nv_bfloat16* __restrict__ k,
                 const __nv_bfloat16* __restrict__ v, float* __restrict__ out)
{
    extern __shared__ char smraw[];
    __nv_bfloat16* Qs = (__nv_bfloat16*)(smraw + AQ_);
    __nv_bfloat16* Ks = (__nv_bfloat16*)(smraw + AK_);
    __nv_bfloat16* Vs = (__nv_bfloat16*)(smraw + AV_);
    float*         Sfp = (float*)(smraw + ASF_);
    float*         Osm = (float*)(smraw + ASF_);
    __nv_bfloat16* Stb = (__nv_bfloat16*)(smraw + AST2);

    int blk = blockIdx.x;
    int tb = blk >> 3, h = blk & 7;
    size_t base = ((size_t)tb * C_ + h * D_) * N_;
    int tid = threadIdx.x;
    int wid = tid >> 5;

    const __nv_bfloat16* srcs[3] = { q + base, k + base, v + base };
    __nv_bfloat16* dsts[3] = { Qs, Ks, Vs };
#pragma unroll
    for (int mtx = 0; mtx < 3; mtx++) {
#pragma unroll
        for (int u = 0; u < 6; u++) {
            int idx = tid + u * 256;
            int r = idx >> 5, col = (idx & 31) << 3;
            *(uint4*)(dsts[mtx] + r * LDQ + col) = *(const uint4*)(srcs[mtx] + (size_t)r * N_ + col);
        }
    }
#pragma unroll
    for (int u = 0; u < 2; u++) {
        int idx = tid + u * 256;
        int r = 48 + (idx >> 5), col = (idx & 31) << 3;
        *(uint4*)(Vs + r * LDQ + col) = make_uint4(0, 0, 0, 0);
    }
    __syncthreads();

#pragma unroll 1
    for (int nt = 0; nt < 4; nt++) {
        int n0 = nt * 64;

        {
            int wm2 = wid & 3;
            int wn2 = wid >> 2;
            wmma::fragment<wmma::accumulator, 16, 16, 16, float> sacc[4][2];
#pragma unroll
            for (int i = 0; i < 4; i++)
#pragma unroll
                for (int j = 0; j < 2; j++) wmma::fill_fragment(sacc[i][j], 0.f);
#pragma unroll
            for (int dk = 0; dk < 48; dk += 16) {
                wmma::fragment<wmma::matrix_a, 16, 16, 16, __nv_bfloat16, wmma::col_major> ak[4];
                wmma::fragment<wmma::matrix_b, 16, 16, 16, __nv_bfloat16, wmma::row_major> bq[2];
#pragma unroll
                for (int i = 0; i < 4; i++)
                    wmma::load_matrix_sync(ak[i], Ks + dk * LDQ + wm2 * 64 + i * 16, LDQ);
#pragma unroll
                for (int j = 0; j < 2; j++)
                    wmma::load_matrix_sync(bq[j], Qs + dk * LDQ + n0 + wn2 * 32 + j * 16, LDQ);
#pragma unroll
                for (int i = 0; i < 4; i++)
#pragma unroll
                    for (int j = 0; j < 2; j++)
                        wmma::mma_sync(sacc[i][j], ak[i], bq[j], sacc[i][j]);
            }
#pragma unroll
            for (int i = 0; i < 4; i++)
#pragma unroll
                for (int j = 0; j < 2; j++)
                    wmma::store_matrix_sync(Sfp + (wm2 * 64 + i * 16) * LDSF + wn2 * 32 + j * 16,
                                            sacc[i][j], LDSF, wmma::mem_row_major);
        }
        __syncthreads();

#pragma unroll
        for (int u = 0; u < 16; u++) {
            int idx = tid + u * 256;
            int m = idx >> 4, c4 = (idx & 15) << 2;
            float4 val = *(float4*)(Sfp + m * LDSF + c4);
            __nv_bfloat162 p0 = __floats2bfloat162_rn(val.x, val.y);
            __nv_bfloat162 p1 = __floats2bfloat162_rn(val.z, val.w);
            uint2 w;
            w.x = *(unsigned int*)&p0;
            w.y = *(unsigned int*)&p1;
            *(uint2*)(Stb + m * LDS2 + c4) = w;
        }
        __syncthreads();

        {
            int dr = wid & 1;
            int nc = wid >> 1;
            wmma::fragment<wmma::accumulator, 16, 16, 16, float> oacc[2];
#pragma unroll
            for (int i = 0; i < 2; i++) wmma::fill_fragment(oacc[i], 0.f);
#pragma unroll
            for (int m = 0; m < 256; m += 16) {
                wmma::fragment<wmma::matrix_a, 16, 16, 16, __nv_bfloat16, wmma::row_major> av[2];
                wmma::fragment<wmma::matrix_b, 16, 16, 16, __nv_bfloat16, wmma::row_major> bs;
#pragma unroll
                for (int i = 0; i < 2; i++)
                    wmma::load_matrix_sync(av[i], Vs + (dr * 32 + i * 16) * LDQ + m, LDQ);
                wmma::load_matrix_sync(bs, Stb + m * LDS2 + nc * 16, LDS2);
#pragma unroll
                for (int i = 0; i < 2; i++)
                    wmma::mma_sync(oacc[i], av[i], bs, oacc[i]);
            }
#pragma unroll
            for (int i = 0; i < 2; i++)
                wmma::store_matrix_sync(Osm + (dr * 32 + i * 16) * LDO + nc * 16,
                                        oacc[i], LDO, wmma::mem_row_major);
        }
        __syncthreads();

#pragma unroll
        for (int u = 0; u < 3; u++) {
            int e = tid + u * 256;
            int d = e >> 4, c4 = (e & 15) << 2;
            float4 val = *(float4*)(Osm + d * LDO + c4);
            val.x *= 0.125f; val.y *= 0.125f; val.z *= 0.125f; val.w *= 0.125f;
            *(float4*)(out + base + (size_t)d * N_ + n0 + c4) = val;
        }
        __syncthreads();
    }
}

// ---------------- launch ----------------------------------------------------------
extern "C" void kernel_launch(void* const* d_in, const int* in_sizes, int n_in,
                              void* d_out, int out_size)
{
    const float* x   = (const float*)d_in[0];
    const float* qw  = (const float*)d_in[2];
    const float* qg  = (const float*)d_in[3];
    const float* qb  = (const float*)d_in[4];
    const float* qm  = (const float*)d_in[5];
    const float* qv  = (const float*)d_in[6];
    const float* kw  = (const float*)d_in[7];
    const float* kg  = (const float*)d_in[8];
    const float* kb  = (const float*)d_in[9];
    const float* km  = (const float*)d_in[10];
    const float* kv  = (const float*)d_in[11];
    const float* vw  = (const float*)d_in[12];
    const float* vg  = (const float*)d_in[13];
    const float* vb  = (const float*)d_in[14];
    const float* vm  = (const float*)d_in[15];
    const float* vv  = (const float*)d_in[16];
    const float* pw  = (const float*)d_in[17];
    const float* pbias = (const float*)d_in[18];
    const float* pg  = (const float*)d_in[19];
    const float* pb  = (const float*)d_in[20];
    const float* pm  = (const float*)d_in[21];
    const float* pv  = (const float*)d_in[22];

    void *ps1, *psq, *psk, *psv, *ps2, *pya, *phi, *plo;
    cudaGetSymbolAddress(&ps1, g_s1);
    cudaGetSymbolAddress(&psq, g_sq);
    cudaGetSymbolAddress(&psk, g_sk);
    cudaGetSymbolAddress(&psv, g_sv);
    cudaGetSymbolAddress(&ps2, g_s2);
    cudaGetSymbolAddress(&pya, g_ya);
    cudaGetSymbolAddress(&phi, g_whi);
    cudaGetSymbolAddress(&plo, g_wlo);
    __nv_bfloat16* s1  = (__nv_bfloat16*)ps1;
    __nv_bfloat16* sq  = (__nv_bfloat16*)psq;
    __nv_bfloat16* sk  = (__nv_bfloat16*)psk;
    __nv_bfloat16* sv  = (__nv_bfloat16*)psv;
    __nv_bfloat16* s2  = (__nv_bfloat16*)ps2;
    float*         ya  = (float*)pya;
    __nv_bfloat16* whi = (__nv_bfloat16*)phi;
    __nv_bfloat16* wlo = (__nv_bfloat16*)plo;

    cudaFuncSetAttribute(gemm_lif_kernel, cudaFuncAttributeMaxDynamicSharedMemorySize, FSM);
    cudaFuncSetAttribute(gemm_bn_kernel, cudaFuncAttributeMaxDynamicSharedMemorySize, GSM);
    cudaFuncSetAttribute(attn_kernel, cudaFuncAttributeMaxDynamicSharedMemorySize, ASM_);

    // prep: BN fold first (wconv consumes g_bns)
    bnfold_kernel<<<6, 256>>>(qg, qb, qm, qv, kg, kb, km, kv,
                              vg, vb, vm, vv, pg, pb, pm, pv, pbias);
    wconv_kernel<<<(4 * C_ * C_ + 255) / 256, 256>>>(qw, kw, vw, pw);
    // proj_lif on input
    lif_kernel<<<BCN_ / 256, 256>>>(x, s1);
    // fused q,k,v GEMM + bias-MMA + LIF (A-resident)
    gemm_lif_kernel<<<dim3(M3_ / FBM, 1, B_), 256, FSM>>>(
        whi, wlo, s1, sq, sk, sv);
    // bf16 tensor attention -> fp32
    attn_kernel<<<TBH_, 256, ASM_>>>(sq, sk, sv, ya);
    // attn_lif
    lif_kernel<<<BCN_ / 256, 256>>>(ya, s2);
    // proj GEMM + bias + BN -> final output
    gemm_bn_kernel<<<dim3(C_ / GBM, 1, TB_), 256, GSM>>>(
        whi + 3 * C_ * C_, wlo + 3 * C_ * C_, s2, C_, 3 * C_, (float*)d_out);
}

// round 16
// speedup vs baseline: 1.0482x; 1.0197x over previous
#include <cuda_runtime.h>
#include <cuda_bf16.h>
#include <mma.h>
#include <cstdint>

using namespace nvcuda;

#define T_   4
#define B_   32
#define C_   384
#define N_   256
#define H_   8
#define D_   48
#define TB_  (T_ * B_)
#define TBH_ (TB_ * H_)
#define BCN_ (B_ * C_ * N_)      // 3,145,728
#define TOT_ (T_ * BCN_)         // 12,582,912
#define M3_  (3 * C_)            // 1152

// ---------------- scratch (device globals) ----------------------------------------
__device__ __nv_bfloat16 g_s1[TOT_];           // spikes after lif1   [tb][c][n]
__device__ __nv_bfloat16 g_sq[TOT_];           // q spikes            [tb][c][n]
__device__ __nv_bfloat16 g_sk[TOT_];
__device__ __nv_bfloat16 g_sv[TOT_];
__device__ __nv_bfloat16 g_s2[TOT_];           // attn-lif spikes
__device__ float         g_ya[TOT_];           // attention out fp32  [tb][c][n]
__device__ __nv_bfloat16 g_whi[4 * C_ * C_];   // hi bf16 of BN-scaled weights
__device__ __nv_bfloat16 g_wlo[4 * C_ * C_];   // lo residual
__device__ float         g_bns[4 * C_];        // folded BN scale
__device__ float         g_bnb[4 * C_];        // folded BN shift

// ---------------- prep ------------------------------------------------------------
__global__ void bnfold_kernel(const float* qg, const float* qb, const float* qm, const float* qv,
                              const float* kg, const float* kb, const float* km, const float* kv,
                              const float* vg, const float* vb, const float* vm, const float* vv,
                              const float* pg, const float* pb, const float* pm, const float* pv,
                              const float* pbias)
{
    int i = blockIdx.x * 256 + threadIdx.x;
    if (i >= 4 * C_) return;
    int s = i / C_, c = i - s * C_;
    const float *G, *Bt, *M, *V;
    if      (s == 0) { G = qg; Bt = qb; M = qm; V = qv; }
    else if (s == 1) { G = kg; Bt = kb; M = km; V = kv; }
    else if (s == 2) { G = vg; Bt = vb; M = vm; V = vv; }
    else             { G = pg; Bt = pb; M = pm; V = pv; }
    float inv = G[c] / sqrtf(V[c] + 1e-5f);
    float add = Bt[c] - M[c] * inv;
    if (s == 3) add += pbias[c] * inv;
    g_bns[i] = inv;
    g_bnb[i] = add;
}

__global__ void wconv_kernel(const float* __restrict__ w0, const float* __restrict__ w1,
                             const float* __restrict__ w2, const float* __restrict__ w3)
{
    int i = blockIdx.x * 256 + threadIdx.x;
    if (i >= 4 * C_ * C_) return;
    int s = i / (C_ * C_);
    int j = i - s * (C_ * C_);
    int o = j / C_;
    const float* w = (s == 0) ? w0 : (s == 1) ? w1 : (s == 2) ? w2 : w3;
    float val = w[j] * g_bns[s * C_ + o];
    __nv_bfloat16 hi = __float2bfloat16(val);
    g_whi[i] = hi;
    g_wlo[i] = __float2bfloat16(val - __bfloat162float(hi));
}

// ---------------- LIF (streaming) --------------------------------------------------
__global__ void lif_kernel(const float* __restrict__ xin, __nv_bfloat16* __restrict__ sout)
{
    int i = blockIdx.x * 256 + threadIdx.x;
    if (i >= BCN_) return;
    float v = 0.f;
#pragma unroll
    for (int t = 0; t < T_; t++) {
        float xv = xin[(size_t)t * BCN_ + i];
        float h = v + (xv - v) * 0.5f;
        bool sp = (h >= 1.0f);
        sout[(size_t)t * BCN_ + i] = __float2bfloat16(sp ? 1.f : 0.f);
        v = sp ? 0.f : h;
    }
}

// ---------------- cp.async helpers ------------------------------------------------
__device__ __forceinline__ void cpa16(void* s, const void* g)
{
    unsigned int sa = (unsigned int)__cvta_generic_to_shared(s);
    asm volatile("cp.async.cg.shared.global [%0], [%1], 16;\n" :: "r"(sa), "l"(g));
}
__device__ __forceinline__ void cpa_commit() { asm volatile("cp.async.commit_group;\n"); }
template <int NN>
__device__ __forceinline__ void cpa_wait() { asm volatile("cp.async.wait_group %0;\n" :: "n"(NN)); }

// ---------------- fused qkv GEMM + bias-MMA + LIF (A-resident, identical R15) -----
#define FBM 64
#define FBN 256
#define FBK 64
#define FLDA 72
#define FLDB 264
#define FLDC2 132
#define FNT 6
#define FA_KT (FBM * FLDA)
#define FA_LOBASE (6 * FA_KT)
#define FB_BASE (2 * FA_LOBASE)
#define FBST (FBK * FLDB)
#define FCS_B (FB_BASE * 2 + 2 * FBST * 2)
#define FBIAS_B 211968
#define FONES_B 216064
#define FSM 224512

__global__ __launch_bounds__(256, 1)
void gemm_lif_kernel(const __nv_bfloat16* __restrict__ Ahi,
                     const __nv_bfloat16* __restrict__ Alo,
                     const __nv_bfloat16* __restrict__ Bmat,
                     __nv_bfloat16* __restrict__ oq,
                     __nv_bfloat16* __restrict__ ok,
                     __nv_bfloat16* __restrict__ ov)
{
    extern __shared__ char smem[];
    __nv_bfloat16* As = (__nv_bfloat16*)smem;
    __nv_bfloat16* Bs = As + FB_BASE;
    float*         Cs = (float*)(smem + FCS_B);
    __nv_bfloat16* Bh = (__nv_bfloat16*)(smem + FBIAS_B);
    __nv_bfloat16* Bl = Bh + 64 * 16;
    __nv_bfloat16* On = (__nv_bfloat16*)(smem + FONES_B);

    int o0 = blockIdx.x * FBM;
    int b  = blockIdx.z;
    int s  = o0 / C_;
    int oc0 = o0 - s * C_;
    __nv_bfloat16* outp = (s == 0) ? oq : (s == 1) ? ok : ov;

    int tid = threadIdx.x;
    int wid = tid >> 5;
    int wm = wid & 1;
    int wn = wid >> 1;

#pragma unroll
    for (int u = 0; u < 4; u++) {
        int idx = tid + u * 256;
        int r = idx >> 4, c = idx & 15;
        float bv = (c == 0) ? g_bnb[o0 + r] : 0.f;
        __nv_bfloat16 hh = __float2bfloat16(bv);
        Bh[idx] = hh;
        Bl[idx] = __float2bfloat16(bv - __bfloat162float(hh));
    }
    for (int idx = tid; idx < 16 * 264; idx += 256) {
        int r = idx / 264, c = idx - r * 264;
        On[idx] = __float2bfloat16((r == 0 && c < 256) ? 1.f : 0.f);
    }

#pragma unroll
    for (int u = 0; u < 12; u++) {
        int idx = tid + u * 256;
        int kt = idx >> 9;
        int r = (idx >> 3) & 63;
        int c8 = (idx & 7) << 3;
        size_t go = (size_t)(o0 + r) * C_ + kt * FBK + c8;
        cpa16(As + kt * FA_KT + r * FLDA + c8, Ahi + go);
        cpa16(As + FA_LOBASE + kt * FA_KT + r * FLDA + c8, Alo + go);
    }
    cpa_commit();
    __syncthreads();

    float vm[2][4][8];
#pragma unroll
    for (int i = 0; i < 2; i++)
#pragma unroll
        for (int j = 0; j < 4; j++)
#pragma unroll
            for (int e = 0; e < 8; e++) vm[i][j][e] = 0.f;

    auto fillB = [&](const __nv_bfloat16* Bp, int kt, int st) {
        __nv_bfloat16* Bd = Bs + st * FBST;
        int ka = kt * FBK;
#pragma unroll
        for (int u = 0; u < 8; u++) {
            int idx = tid + u * 256;
            int r = idx >> 5, c8 = (idx & 31) << 3;
            cpa16(Bd + r * FLDB + c8, Bp + (size_t)(ka + r) * N_ + c8);
        }
        cpa_commit();
    };

    {
        const __nv_bfloat16* Bp0 = Bmat + (size_t)(0 * B_ + b) * C_ * N_;
        fillB(Bp0, 0, 0);
        fillB(Bp0, 1, 1);
    }

#pragma unroll 1
    for (int t = 0; t < T_; t++) {
        const __nv_bfloat16* Bp = Bmat + (size_t)(t * B_ + b) * C_ * N_;

        wmma::fragment<wmma::accumulator, 16, 16, 16, float> acc[2][4];
        {
            wmma::fragment<wmma::matrix_b, 16, 16, 16, __nv_bfloat16, wmma::row_major> onef;
            wmma::load_matrix_sync(onef, On, 264);
            wmma::fragment<wmma::matrix_a, 16, 16, 16, __nv_bfloat16, wmma::row_major> bh[2], bl2[2];
#pragma unroll
            for (int i = 0; i < 2; i++) {
                wmma::load_matrix_sync(bh[i],  Bh + (wm * 32 + i * 16) * 16, 16);
                wmma::load_matrix_sync(bl2[i], Bl + (wm * 32 + i * 16) * 16, 16);
            }
#pragma unroll
            for (int i = 0; i < 2; i++)
#pragma unroll
                for (int j = 0; j < 4; j++) {
                    wmma::fill_fragment(acc[i][j], 0.f);
                    wmma::mma_sync(acc[i][j], bh[i],  onef, acc[i][j]);
                    wmma::mma_sync(acc[i][j], bl2[i], onef, acc[i][j]);
                }
        }

        for (int kt = 0; kt < FNT; kt++) {
            if (kt + 1 < FNT) cpa_wait<1>(); else cpa_wait<0>();
            __syncthreads();
            const __nv_bfloat16* Ah = As + kt * FA_KT;
            const __nv_bfloat16* Al = As + FA_LOBASE + kt * FA_KT;
            const __nv_bfloat16* Bb = Bs + (kt % 3) * FBST;
#pragma unroll
            for (int ks = 0; ks < 4; ks++) {
                wmma::fragment<wmma::matrix_b, 16, 16, 16, __nv_bfloat16, wmma::row_major> bfr[4];
#pragma unroll
                for (int j = 0; j < 4; j++)
                    wmma::load_matrix_sync(bfr[j], Bb + (ks * 16) * FLDB + wn * 64 + j * 16, FLDB);
                wmma::fragment<wmma::matrix_a, 16, 16, 16, __nv_bfloat16, wmma::row_major> af[2];
#pragma unroll
                for (int i = 0; i < 2; i++)
                    wmma::load_matrix_sync(af[i], Ah + (wm * 32 + i * 16) * FLDA + ks * 16, FLDA);
#pragma unroll
                for (int i = 0; i < 2; i++)
#pragma unroll
                    for (int j = 0; j < 4; j++)
                        wmma::mma_sync(acc[i][j], af[i], bfr[j], acc[i][j]);
#pragma unroll
                for (int i = 0; i < 2; i++)
                    wmma::load_matrix_sync(af[i], Al + (wm * 32 + i * 16) * FLDA + ks * 16, FLDA);
#pragma unroll
                for (int i = 0; i < 2; i++)
#pragma unroll
                    for (int j = 0; j < 4; j++)
                        wmma::mma_sync(acc[i][j], af[i], bfr[j], acc[i][j]);
            }
            if (kt + 2 < FNT) fillB(Bp, kt + 2, (kt + 2) % 3);
        }
        __syncthreads();

        if (t + 1 < T_) {
            const __nv_bfloat16* Bp1 = Bmat + (size_t)((t + 1) * B_ + b) * C_ * N_;
            fillB(Bp1, 0, 0);
        }

#pragma unroll
        for (int i = 0; i < 2; i++)
#pragma unroll
            for (int j = 0; j < 4; j++)
#pragma unroll
                for (int e = 0; e < 8; e++) {
                    float y = acc[i][j].x[e];
                    float m = vm[i][j][e];
                    float hh = m + (y - m) * 0.5f;
                    bool sp = (hh >= 1.0f);
                    vm[i][j][e] = sp ? 0.f : hh;
                    acc[i][j].x[e] = sp ? 1.f : 0.f;
                }

        size_t obase = (size_t)(t * B_ + b) * C_ * N_;
#pragma unroll 1
        for (int hhalf = 0; hhalf < 2; hhalf++) {
            if ((wn >> 1) == hhalf) {
                int wnl = wn & 1;
#pragma unroll
                for (int i = 0; i < 2; i++)
#pragma unroll
                    for (int j = 0; j < 4; j++)
                        wmma::store_matrix_sync(Cs + (wm * 32 + i * 16) * FLDC2 + wnl * 64 + j * 16,
                                                acc[i][j], FLDC2, wmma::mem_row_major);
            }
            __syncthreads();
#pragma unroll
            for (int u = 0; u < 8; u++) {
                int e = tid + u * 256;
                int r = e >> 5;
                int c4 = (e & 31) << 2;
                int cg = hhalf * 128 + c4;
                float4 val = *(float4*)(Cs + r * FLDC2 + c4);
                __nv_bfloat162 p0 = __floats2bfloat162_rn(val.x, val.y);
                __nv_bfloat162 p1 = __floats2bfloat162_rn(val.z, val.w);
                uint2 w;
                w.x = *(unsigned int*)&p0;
                w.y = *(unsigned int*)&p1;
                *(uint2*)(outp + obase + (size_t)(oc0 + r) * N_ + cg) = w;
            }
            __syncthreads();
        }

        if (t + 1 < T_) {
            const __nv_bfloat16* Bp1 = Bmat + (size_t)((t + 1) * B_ + b) * C_ * N_;
            fillB(Bp1, 1, 1);
        }
    }
}

// ---------------- proj GEMM + folded BN (identical to R8) -------------------------
#define GBM 128
#define GBN 256
#define GBK 64
#define LDA 72
#define LDB 264
#define LDC 260
#define NT_ 6
#define A_ST (GBM * LDA)
#define AST (2 * A_ST)
#define BST (GBK * LDB)
#define STG_ (AST + BST)
#define GSM (3 * STG_ * 2)                // 211968 B

__global__ __launch_bounds__(256, 1)
void gemm_bn_kernel(const __nv_bfloat16* __restrict__ Ahi,
                    const __nv_bfloat16* __restrict__ Alo,
                    const __nv_bfloat16* __restrict__ Bmat,
                    int ldo, int bnoff, float* __restrict__ out)
{
    extern __shared__ char smem[];
    __nv_bfloat16* Sg = (__nv_bfloat16*)smem;
    float*         Cs = (float*)smem;

    int o0 = blockIdx.x * GBM;
    int tb = blockIdx.z;
    const __nv_bfloat16* Bp = Bmat + (size_t)tb * C_ * N_;
    int tid = threadIdx.x;
    int wid = tid >> 5;
    int wm = wid & 1;
    int wn = wid >> 1;

    wmma::fragment<wmma::accumulator, 16, 16, 16, float> acc[4][4];
#pragma unroll
    for (int i = 0; i < 4; i++)
#pragma unroll
        for (int j = 0; j < 4; j++) wmma::fill_fragment(acc[i][j], 0.f);

    auto fill = [&](int kt, int st) {
        __nv_bfloat16* Ah = Sg + st * STG_;
        __nv_bfloat16* Al = Ah + A_ST;
        __nv_bfloat16* Bd = Ah + AST;
        int ka = kt * GBK;
#pragma unroll
        for (int u = 0; u < 4; u++) {
            int idx = tid + u * 256;
            int r = idx >> 3, c8 = (idx & 7) << 3;
            size_t go = (size_t)(o0 + r) * C_ + ka + c8;
            cpa16(Ah + r * LDA + c8, Ahi + go);
            cpa16(Al + r * LDA + c8, Alo + go);
        }
#pragma unroll
        for (int u = 0; u < 8; u++) {
            int idx = tid + u * 256;
            int r = idx >> 5, c8 = (idx & 31) << 3;
            cpa16(Bd + r * LDB + c8, Bp + (size_t)(ka + r) * N_ + c8);
        }
        cpa_commit();
    };

    fill(0, 0);
    fill(1, 1);
    for (int kt = 0; kt < NT_; kt++) {
        if (kt + 1 < NT_) cpa_wait<1>(); else cpa_wait<0>();
        __syncthreads();
        int st = kt % 3;
        const __nv_bfloat16* Ah = Sg + st * STG_;
        const __nv_bfloat16* Al = Ah + A_ST;
        const __nv_bfloat16* Bb = Ah + AST;
#pragma unroll
        for (int ks = 0; ks < 4; ks++) {
            wmma::fragment<wmma::matrix_b, 16, 16, 16, __nv_bfloat16, wmma::row_major> bfr[4];
#pragma unroll
            for (int j = 0; j < 4; j++)
                wmma::load_matrix_sync(bfr[j], Bb + (ks * 16) * LDB + wn * 64 + j * 16, LDB);
            wmma::fragment<wmma::matrix_a, 16, 16, 16, __nv_bfloat16, wmma::row_major> af[4];
#pragma unroll
            for (int i = 0; i < 4; i++)
                wmma::load_matrix_sync(af[i], Ah + (wm * 64 + i * 16) * LDA + ks * 16, LDA);
#pragma unroll
            for (int i = 0; i < 4; i++)
#pragma unroll
                for (int j = 0; j < 4; j++)
                    wmma::mma_sync(acc[i][j], af[i], bfr[j], acc[i][j]);
#pragma unroll
            for (int i = 0; i < 4; i++)
                wmma::load_matrix_sync(af[i], Al + (wm * 64 + i * 16) * LDA + ks * 16, LDA);
#pragma unroll
            for (int i = 0; i < 4; i++)
#pragma unroll
                for (int j = 0; j < 4; j++)
                    wmma::mma_sync(acc[i][j], af[i], bfr[j], acc[i][j]);
        }
        if (kt + 2 < NT_) fill(kt + 2, (kt + 2) % 3);
    }
    __syncthreads();

#pragma unroll
    for (int i = 0; i < 4; i++)
#pragma unroll
        for (int j = 0; j < 4; j++)
            wmma::store_matrix_sync(Cs + (wm * 64 + i * 16) * LDC + wn * 64 + j * 16,
                                    acc[i][j], LDC, wmma::mem_row_major);
    __syncthreads();

#pragma unroll
    for (int u = 0; u < 32; u++) {
        int e = tid + u * 256;
        int r = e >> 6;
        int c4 = (e & 63) << 2;
        int o = o0 + r;
        float add = g_bnb[bnoff + o];
        float4 val = *(float4*)(Cs + r * LDC + c4);
        val.x += add; val.y += add; val.z += add; val.w += add;
        *(float4*)(out + ((size_t)tb * ldo + o) * N_ + c4) = val;
    }
}

// ---------------- tensor-core attention (128-wide stage 2) ------------------------
// Per (t,b,h): two 128-wide n-chunks. Each chunk: 2x stage1 (64-wide) -> bf16 St
// [256m][128n], then ONE stage2 O[64d][128n] = V.St with 2(d)x4(n) warps, acc[2][2].
#define YLD  264    // K/V/Q row pitch (256 + 8)
#define YLDS 68     // Sfp fp32 pitch (64 + 4)
#define YLDT 136    // Stb bf16 pitch (128 + 8)
#define YLDO 132    // Osm fp32 pitch (128 + 4)
#define YK_  0
#define YV_  (48 * YLD * 2)                 // 25344
#define YQ_  (YV_ + 64 * YLD * 2)           // 59136
#define YSF_ (YQ_ + 48 * YLD * 2)           // 84480 (Osm alias)
#define YST_ (YSF_ + 256 * YLDS * 4)        // 154112
#define YSM  (YST_ + 256 * YLDT * 2)        // 223744 B

__global__ __launch_bounds__(256)
void attn_kernel(const __nv_bfloat16* __restrict__ q, const __nv_bfloat16* __restrict__ k,
                 const __nv_bfloat16* __restrict__ v, float* __restrict__ out)
{
    extern __shared__ char smraw[];
    __nv_bfloat16* Ks = (__nv_bfloat16*)(smraw + YK_);   // [48][264]
    __nv_bfloat16* Vs = (__nv_bfloat16*)(smraw + YV_);   // [64][264] rows 48..63 zero
    __nv_bfloat16* Qs = (__nv_bfloat16*)(smraw + YQ_);   // [48][264]
    float*         Sfp = (float*)(smraw + YSF_);         // [256][68]
    float*         Osm = (float*)(smraw + YSF_);         // alias
    __nv_bfloat16* Stb = (__nv_bfloat16*)(smraw + YST_); // [256][136]

    int blk = blockIdx.x;
    int tb = blk >> 3, h = blk & 7;
    size_t base = ((size_t)tb * C_ + h * D_) * N_;
    int tid = threadIdx.x;
    int wid = tid >> 5;

    // load K, V, Q head slices [48][256]; V rows 48..63 zeroed
    const __nv_bfloat16* srcs[3] = { k + base, v + base, q + base };
    __nv_bfloat16* dsts[3] = { Ks, Vs, Qs };
#pragma unroll
    for (int mtx = 0; mtx < 3; mtx++) {
#pragma unroll
        for (int u = 0; u < 6; u++) {
            int idx = tid + u * 256;
            int r = idx >> 5, col = (idx & 31) << 3;
            *(uint4*)(dsts[mtx] + r * YLD + col) = *(const uint4*)(srcs[mtx] + (size_t)r * N_ + col);
        }
    }
#pragma unroll
    for (int u = 0; u < 2; u++) {
        int idx = tid + u * 256;
        int r = 48 + (idx >> 5), col = (idx & 31) << 3;
        *(uint4*)(Vs + r * YLD + col) = make_uint4(0, 0, 0, 0);
    }
    __syncthreads();

#pragma unroll 1
    for (int np = 0; np < 2; np++) {
        // ---- stage 1 twice: St[256m][128n] built 64 cols at a time ----
#pragma unroll 1
        for (int nt2 = 0; nt2 < 2; nt2++) {
            int n0 = np * 128 + nt2 * 64;
            {
                int wm2 = wid & 3;      // m, 64 rows each
                int wn2 = wid >> 2;     // n', 32 cols each
                wmma::fragment<wmma::accumulator, 16, 16, 16, float> sacc[4][2];
#pragma unroll
                for (int i = 0; i < 4; i++)
#pragma unroll
                    for (int j = 0; j < 2; j++) wmma::fill_fragment(sacc[i][j], 0.f);
#pragma unroll
                for (int dk = 0; dk < 48; dk += 16) {
                    wmma::fragment<wmma::matrix_a, 16, 16, 16, __nv_bfloat16, wmma::col_major> ak[4];
                    wmma::fragment<wmma::matrix_b, 16, 16, 16, __nv_bfloat16, wmma::row_major> bq[2];
#pragma unroll
                    for (int i = 0; i < 4; i++)
                        wmma::load_matrix_sync(ak[i], Ks + dk * YLD + wm2 * 64 + i * 16, YLD);
#pragma unroll
                    for (int j = 0; j < 2; j++)
                        wmma::load_matrix_sync(bq[j], Qs + dk * YLD + n0 + wn2 * 32 + j * 16, YLD);
#pragma unroll
                    for (int i = 0; i < 4; i++)
#pragma unroll
                        for (int j = 0; j < 2; j++)
                            wmma::mma_sync(sacc[i][j], ak[i], bq[j], sacc[i][j]);
                }
#pragma unroll
                for (int i = 0; i < 4; i++)
#pragma unroll
                    for (int j = 0; j < 2; j++)
                        wmma::store_matrix_sync(Sfp + (wm2 * 64 + i * 16) * YLDS + wn2 * 32 + j * 16,
                                                sacc[i][j], YLDS, wmma::mem_row_major);
            }
            __syncthreads();

            // convert 64-col chunk -> Stb at col offset nt2*64 (exact: ints <= 48)
#pragma unroll
            for (int u = 0; u < 16; u++) {
                int idx = tid + u * 256;
                int m = idx >> 4, c4 = (idx & 15) << 2;
                float4 val = *(float4*)(Sfp + m * YLDS + c4);
                __nv_bfloat162 p0 = __floats2bfloat162_rn(val.x, val.y);
                __nv_bfloat162 p1 = __floats2bfloat162_rn(val.z, val.w);
                uint2 w;
                w.x = *(unsigned int*)&p0;
                w.y = *(unsigned int*)&p1;
                *(uint2*)(Stb + m * YLDT + nt2 * 64 + c4) = w;
            }
            __syncthreads();
        }

        // ---- stage 2: O[64d][128n] = V . St  (2d x 4n warps, acc[2][2]) ----
        {
            int dr = wid & 1;       // d, 32 rows each
            int nc = wid >> 1;      // n, 32 cols each
            wmma::fragment<wmma::accumulator, 16, 16, 16, float> oacc[2][2];
#pragma unroll
            for (int i = 0; i < 2; i++)
#pragma unroll
                for (int j = 0; j < 2; j++) wmma::fill_fragment(oacc[i][j], 0.f);
#pragma unroll
            for (int m = 0; m < 256; m += 16) {
                wmma::fragment<wmma::matrix_a, 16, 16, 16, __nv_bfloat16, wmma::row_major> av[2];
                wmma::fragment<wmma::matrix_b, 16, 16, 16, __nv_bfloat16, wmma::row_major> bs[2];
#pragma unroll
                for (int i = 0; i < 2; i++)
                    wmma::load_matrix_sync(av[i], Vs + (dr * 32 + i * 16) * YLD + m, YLD);
#pragma unroll
                for (int j = 0; j < 2; j++)
                    wmma::load_matrix_sync(bs[j], Stb + m * YLDT + nc * 32 + j * 16, YLDT);
#pragma unroll
                for (int i = 0; i < 2; i++)
#pragma unroll
                    for (int j = 0; j < 2; j++)
                        wmma::mma_sync(oacc[i][j], av[i], bs[j], oacc[i][j]);
            }
#pragma unroll
            for (int i = 0; i < 2; i++)
#pragma unroll
                for (int j = 0; j < 2; j++)
                    wmma::store_matrix_sync(Osm + (dr * 32 + i * 16) * YLDO + nc * 32 + j * 16,
                                            oacc[i][j], YLDO, wmma::mem_row_major);
        }
        __syncthreads();

        // ---- write d<48 rows, scaled 0.125 ----
#pragma unroll
        for (int u = 0; u < 6; u++) {
            int e = tid + u * 256;          // 1536 = 48 rows x 32 col-groups
            int d = e >> 5, c4 = (e & 31) << 2;
            float4 val = *(float4*)(Osm + d * YLDO + c4);
            val.x *= 0.125f; val.y *= 0.125f; val.z *= 0.125f; val.w *= 0.125f;
            *(float4*)(out + base + (size_t)d * N_ + np * 128 + c4) = val;
        }
        __syncthreads();
    }
}

// ---------------- launch ----------------------------------------------------------
extern "C" void kernel_launch(void* const* d_in, const int* in_sizes, int n_in,
                              void* d_out, int out_size)
{
    const float* x   = (const float*)d_in[0];
    const float* qw  = (const float*)d_in[2];
    const float* qg  = (const float*)d_in[3];
    const float* qb  = (const float*)d_in[4];
    const float* qm  = (const float*)d_in[5];
    const float* qv  = (const float*)d_in[6];
    const float* kw  = (const float*)d_in[7];
    const float* kg  = (const float*)d_in[8];
    const float* kb  = (const float*)d_in[9];
    const float* km  = (const float*)d_in[10];
    const float* kv  = (const float*)d_in[11];
    const float* vw  = (const float*)d_in[12];
    const float* vg  = (const float*)d_in[13];
    const float* vb  = (const float*)d_in[14];
    const float* vm  = (const float*)d_in[15];
    const float* vv  = (const float*)d_in[16];
    const float* pw  = (const float*)d_in[17];
    const float* pbias = (const float*)d_in[18];
    const float* pg  = (const float*)d_in[19];
    const float* pb  = (const float*)d_in[20];
    const float* pm  = (const float*)d_in[21];
    const float* pv  = (const float*)d_in[22];

    void *ps1, *psq, *psk, *psv, *ps2, *pya, *phi, *plo;
    cudaGetSymbolAddress(&ps1, g_s1);
    cudaGetSymbolAddress(&psq, g_sq);
    cudaGetSymbolAddress(&psk, g_sk);
    cudaGetSymbolAddress(&psv, g_sv);
    cudaGetSymbolAddress(&ps2, g_s2);
    cudaGetSymbolAddress(&pya, g_ya);
    cudaGetSymbolAddress(&phi, g_whi);
    cudaGetSymbolAddress(&plo, g_wlo);
    __nv_bfloat16* s1  = (__nv_bfloat16*)ps1;
    __nv_bfloat16* sq  = (__nv_bfloat16*)psq;
    __nv_bfloat16* sk  = (__nv_bfloat16*)psk;
    __nv_bfloat16* sv  = (__nv_bfloat16*)psv;
    __nv_bfloat16* s2  = (__nv_bfloat16*)ps2;
    float*         ya  = (float*)pya;
    __nv_bfloat16* whi = (__nv_bfloat16*)phi;
    __nv_bfloat16* wlo = (__nv_bfloat16*)plo;

    cudaFuncSetAttribute(gemm_lif_kernel, cudaFuncAttributeMaxDynamicSharedMemorySize, FSM);
    cudaFuncSetAttribute(gemm_bn_kernel, cudaFuncAttributeMaxDynamicSharedMemorySize, GSM);
    cudaFuncSetAttribute(attn_kernel, cudaFuncAttributeMaxDynamicSharedMemorySize, YSM);

    // prep: BN fold first (wconv consumes g_bns)
    bnfold_kernel<<<6, 256>>>(qg, qb, qm, qv, kg, kb, km, kv,
                              vg, vb, vm, vv, pg, pb, pm, pv, pbias);
    wconv_kernel<<<(4 * C_ * C_ + 255) / 256, 256>>>(qw, kw, vw, pw);
    // proj_lif on input
    lif_kernel<<<BCN_ / 256, 256>>>(x, s1);
    // fused q,k,v GEMM + bias-MMA + LIF (A-resident)
    gemm_lif_kernel<<<dim3(M3_ / FBM, 1, B_), 256, FSM>>>(
        whi, wlo, s1, sq, sk, sv);
    // bf16 tensor attention -> fp32
    attn_kernel<<<TBH_, 256, YSM>>>(sq, sk, sv, ya);
    // attn_lif
    lif_kernel<<<BCN_ / 256, 256>>>(ya, s2);
    // proj GEMM + bias + BN -> final output
    gemm_bn_kernel<<<dim3(C_ / GBM, 1, TB_), 256, GSM>>>(
        whi + 3 * C_ * C_, wlo + 3 * C_ * C_, s2, C_, 3 * C_, (float*)d_out);
}